// round 6
// baseline (speedup 1.0000x reference)
#include <cuda_runtime.h>
#include <cuda_bf16.h>
#include <math.h>
#include <stdint.h>

// Problem constants
#define TT 512
#define BB 256
#define IN_DIM 256
#define H1 512
#define HH 256
#define OUT_DIM 18
#define MTOT (TT*BB)   // 131072
#define NCTA 128

// -------------------- scratch (static device globals; no allocs) -----------
__device__ float d_buf1[(size_t)MTOT * 512];     // fc2a out (fp32, for head)
__device__ float d_GI  [(size_t)MTOT * 768];     // gi fp32

__device__ __nv_bfloat16 d_XHI[(size_t)MTOT * 256], d_XLO[(size_t)MTOT * 256];
__device__ __nv_bfloat16 d_A1HI[(size_t)MTOT * 512], d_A1LO[(size_t)MTOT * 512];
__device__ __nv_bfloat16 d_A2HI[(size_t)MTOT * 256], d_A2LO[(size_t)MTOT * 256];
__device__ __nv_bfloat16 d_HHI[(size_t)MTOT * 256], d_HLO[(size_t)MTOT * 256];

__device__ __nv_bfloat16 d_W1AHI[512*256], d_W1ALO[512*256];
__device__ __nv_bfloat16 d_W1BHI[256*512], d_W1BLO[256*512];
__device__ __nv_bfloat16 d_WIHHI[768*256], d_WIHLO[768*256];
__device__ __nv_bfloat16 d_W2AHI[512*256], d_W2ALO[512*256];
__device__ __nv_bfloat16 d_WHHHI[768*256], d_WHHLO[768*256];

__device__ unsigned int d_flags[NCTA];           // grid barrier flags

// ==================== helpers ==============================================
__device__ __forceinline__ uint32_t smem_u32(const void* p) {
    uint32_t a;
    asm("{ .reg .u64 t; cvta.to.shared.u64 t, %1; cvt.u32.u64 %0, t; }"
        : "=r"(a) : "l"(p));
    return a;
}

__device__ __forceinline__ void ldsm4(uint32_t* r, uint32_t addr) {
    asm volatile("ldmatrix.sync.aligned.m8n8.x4.shared.b16 {%0,%1,%2,%3}, [%4];"
        : "=r"(r[0]), "=r"(r[1]), "=r"(r[2]), "=r"(r[3]) : "r"(addr));
}
__device__ __forceinline__ void ldsm2(uint32_t* r, uint32_t addr) {
    asm volatile("ldmatrix.sync.aligned.m8n8.x2.shared.b16 {%0,%1}, [%2];"
        : "=r"(r[0]), "=r"(r[1]) : "r"(addr));
}

__device__ __forceinline__ void mma16816(float* c, const uint32_t* a, const uint32_t* b) {
    asm volatile(
        "mma.sync.aligned.m16n8k16.row.col.f32.bf16.bf16.f32 "
        "{%0,%1,%2,%3}, {%4,%5,%6,%7}, {%8,%9}, {%0,%1,%2,%3};"
        : "+f"(c[0]), "+f"(c[1]), "+f"(c[2]), "+f"(c[3])
        : "r"(a[0]), "r"(a[1]), "r"(a[2]), "r"(a[3]), "r"(b[0]), "r"(b[1]));
}

__device__ __forceinline__ void cp16(uint32_t dst, const void* src) {
    asm volatile("cp.async.cg.shared.global [%0], [%1], 16;"
        :: "r"(dst), "l"(src) : "memory");
}
#define CP_COMMIT() asm volatile("cp.async.commit_group;" ::: "memory")
#define CP_WAIT0()  asm volatile("cp.async.wait_group 0;" ::: "memory")
#define CP_WAIT1()  asm volatile("cp.async.wait_group 1;" ::: "memory")

__device__ __forceinline__ void split_bf16x4(float4 v, uint2& hv, uint2& lv) {
    __nv_bfloat16 h0 = __float2bfloat16(v.x);
    __nv_bfloat16 h1 = __float2bfloat16(v.y);
    __nv_bfloat16 h2 = __float2bfloat16(v.z);
    __nv_bfloat16 h3 = __float2bfloat16(v.w);
    __nv_bfloat16 l0 = __float2bfloat16(v.x - __bfloat162float(h0));
    __nv_bfloat16 l1 = __float2bfloat16(v.y - __bfloat162float(h1));
    __nv_bfloat16 l2 = __float2bfloat16(v.z - __bfloat162float(h2));
    __nv_bfloat16 l3 = __float2bfloat16(v.w - __bfloat162float(h3));
    hv.x = (uint32_t)__bfloat16_as_ushort(h0) | ((uint32_t)__bfloat16_as_ushort(h1) << 16);
    hv.y = (uint32_t)__bfloat16_as_ushort(h2) | ((uint32_t)__bfloat16_as_ushort(h3) << 16);
    lv.x = (uint32_t)__bfloat16_as_ushort(l0) | ((uint32_t)__bfloat16_as_ushort(l1) << 16);
    lv.y = (uint32_t)__bfloat16_as_ushort(l2) | ((uint32_t)__bfloat16_as_ushort(l3) << 16);
}

__device__ __forceinline__ uint32_t pack_hi2(float a, float b, uint32_t& lo) {
    __nv_bfloat16 ha = __float2bfloat16(a);
    __nv_bfloat16 hb = __float2bfloat16(b);
    __nv_bfloat16 la = __float2bfloat16(a - __bfloat162float(ha));
    __nv_bfloat16 lb = __float2bfloat16(b - __bfloat162float(hb));
    lo = (uint32_t)__bfloat16_as_ushort(la) | ((uint32_t)__bfloat16_as_ushort(lb) << 16);
    return (uint32_t)__bfloat16_as_ushort(ha) | ((uint32_t)__bfloat16_as_ushort(hb) << 16);
}

// -------------------- split / zero kernels ---------------------------------
__global__ void split_f32(const float4* __restrict__ in,
                          uint2* __restrict__ hi, uint2* __restrict__ lo, int n4) {
    int i = blockIdx.x * blockDim.x + threadIdx.x;
    if (i < n4) {
        uint2 h, l;
        split_bf16x4(in[i], h, l);
        hi[i] = h; lo[i] = l;
    }
}
__global__ void zero_u32(uint32_t* p, int n) {
    int i = blockIdx.x * blockDim.x + threadIdx.x;
    if (i < n) p[i] = 0u;
}

// ==================== pipelined bf16-split GEMM =============================
#define GROW 144
#define G_AHI 0
#define G_ALO 18432
#define G_BHI 36864
#define G_BLO 55296
#define G_STAGE 73728
#define G_SM_TOTAL (2*G_STAGE)

template<bool RELU, int OUTM>
__global__ void __launch_bounds__(256, 1) gemm_bf(
    const __nv_bfloat16* __restrict__ Ahi, const __nv_bfloat16* __restrict__ Alo,
    const __nv_bfloat16* __restrict__ Bhi, const __nv_bfloat16* __restrict__ Blo,
    const float* __restrict__ bias,
    float* __restrict__ C, __nv_bfloat16* __restrict__ Chi, __nv_bfloat16* __restrict__ Clo,
    int M, int N, int K)
{
    extern __shared__ char sm[];
    const uint32_t smb = smem_u32(sm);
    const int tid = threadIdx.x;
    const int lane = tid & 31;
    const int wid = tid >> 5;
    const int wm = wid & 1;
    const int wn = wid >> 1;
    const int m0 = blockIdx.y * 128;
    const int n0 = blockIdx.x * 128;

    float acc[4][4][4];
    #pragma unroll
    for (int i = 0; i < 4; i++)
        #pragma unroll
        for (int j = 0; j < 4; j++)
            #pragma unroll
            for (int e = 0; e < 4; e++) acc[i][j][e] = 0.f;

    const uint32_t a_row = (uint32_t)(lane & 15);
    const uint32_t a_kb  = (uint32_t)((lane >> 4) * 16);
    const uint32_t b_row = (uint32_t)(((lane >> 4) & 1) * 8 + (lane & 7));
    const uint32_t b_kb  = (uint32_t)(((lane >> 3) & 1) * 16);

    const int nchunks = K >> 6;

    auto load_chunk = [&](int kc, int st) {
        const int kb = kc << 6;
        const uint32_t base = smb + (uint32_t)st * G_STAGE;
        #pragma unroll
        for (int j = 0; j < 4; j++) {
            int idx = tid + 256 * j;
            int r = idx >> 3;
            int c = idx & 7;
            size_t aoff = (size_t)(m0 + r) * K + kb + c * 8;
            size_t boff = (size_t)(n0 + r) * K + kb + c * 8;
            uint32_t d = (uint32_t)(r * GROW + c * 16);
            cp16(base + G_AHI + d, Ahi + aoff);
            cp16(base + G_ALO + d, Alo + aoff);
            cp16(base + G_BHI + d, Bhi + boff);
            cp16(base + G_BLO + d, Blo + boff);
        }
        CP_COMMIT();
    };

    load_chunk(0, 0);

    for (int kc = 0; kc < nchunks; kc++) {
        const int st = kc & 1;
        if (kc + 1 < nchunks) { load_chunk(kc + 1, st ^ 1); CP_WAIT1(); }
        else                  { CP_WAIT0(); }
        __syncthreads();

        const uint32_t base = smb + (uint32_t)st * G_STAGE;
        #pragma unroll
        for (int ks = 0; ks < 4; ks++) {
            const uint32_t koff = (uint32_t)(ks * 32);
            uint32_t afr[4][4], bhi2[4][2], blo2[4][2];

            #pragma unroll
            for (int mt = 0; mt < 4; mt++)
                ldsm4(afr[mt], base + G_AHI + (uint32_t)(wm*64 + mt*16 + a_row)*GROW + koff + a_kb);
            #pragma unroll
            for (int g = 0; g < 2; g++) {
                uint32_t r4[4];
                ldsm4(r4, base + G_BHI + (uint32_t)(wn*32 + g*16 + b_row)*GROW + koff + b_kb);
                bhi2[g*2  ][0] = r4[0]; bhi2[g*2  ][1] = r4[1];
                bhi2[g*2+1][0] = r4[2]; bhi2[g*2+1][1] = r4[3];
            }
            #pragma unroll
            for (int mt = 0; mt < 4; mt++)
                #pragma unroll
                for (int nt = 0; nt < 4; nt++)
                    mma16816(acc[mt][nt], afr[mt], bhi2[nt]);

            #pragma unroll
            for (int g = 0; g < 2; g++) {
                uint32_t r4[4];
                ldsm4(r4, base + G_BLO + (uint32_t)(wn*32 + g*16 + b_row)*GROW + koff + b_kb);
                blo2[g*2  ][0] = r4[0]; blo2[g*2  ][1] = r4[1];
                blo2[g*2+1][0] = r4[2]; blo2[g*2+1][1] = r4[3];
            }
            #pragma unroll
            for (int mt = 0; mt < 4; mt++)
                #pragma unroll
                for (int nt = 0; nt < 4; nt++)
                    mma16816(acc[mt][nt], afr[mt], blo2[nt]);

            #pragma unroll
            for (int mt = 0; mt < 4; mt++)
                ldsm4(afr[mt], base + G_ALO + (uint32_t)(wm*64 + mt*16 + a_row)*GROW + koff + a_kb);
            #pragma unroll
            for (int mt = 0; mt < 4; mt++)
                #pragma unroll
                for (int nt = 0; nt < 4; nt++)
                    mma16816(acc[mt][nt], afr[mt], bhi2[nt]);
        }
        __syncthreads();
    }

    const int r_in = lane >> 2;
    const int c_in = (lane & 3) * 2;
    #pragma unroll
    for (int mt = 0; mt < 4; mt++) {
        #pragma unroll
        for (int nt = 0; nt < 4; nt++) {
            int col = n0 + wn * 32 + nt * 8 + c_in;
            float b0 = bias[col], b1 = bias[col + 1];
            int row0 = m0 + wm * 64 + mt * 16 + r_in;
            float v00 = acc[mt][nt][0] + b0, v01 = acc[mt][nt][1] + b1;
            float v10 = acc[mt][nt][2] + b0, v11 = acc[mt][nt][3] + b1;
            if (RELU) {
                v00 = fmaxf(v00, 0.f); v01 = fmaxf(v01, 0.f);
                v10 = fmaxf(v10, 0.f); v11 = fmaxf(v11, 0.f);
            }
            if (OUTM == 0) {
                float2 p0, p1;
                p0.x = v00; p0.y = v01; p1.x = v10; p1.y = v11;
                *(float2*)&C[(size_t)row0 * N + col] = p0;
                *(float2*)&C[(size_t)(row0 + 8) * N + col] = p1;
            } else {
                uint32_t lo0, lo1;
                uint32_t hi0 = pack_hi2(v00, v01, lo0);
                uint32_t hi1 = pack_hi2(v10, v11, lo1);
                *(uint32_t*)&Chi[(size_t)row0 * N + col] = hi0;
                *(uint32_t*)&Clo[(size_t)row0 * N + col] = lo0;
                *(uint32_t*)&Chi[(size_t)(row0 + 8) * N + col] = hi1;
                *(uint32_t*)&Clo[(size_t)(row0 + 8) * N + col] = lo1;
            }
        }
    }
}

// ==================== persistent GRU kernel =================================
// 128 CTAs (8 b-tiles x 16 k-tiles), 128 threads, all 512 steps in one launch.
// W slice resident in smem; h_prev fp32 lives in registers (stable ownership);
// flag-array grid barrier between steps.
#define U_WHI 0
#define U_WLO 25344            // 48*528
#define U_HHI 50688
#define U_HLO 67584            // 32*528
#define U_GH  84480            // 32*49*4 = 6272
#define U_SM_TOTAL 90752
#define USTRIDE 528

__global__ void __launch_bounds__(128, 1) gru_persist(
    const float* __restrict__ GI_,           // [T*256,768]
    const __nv_bfloat16* __restrict__ whh_hi,
    const __nv_bfloat16* __restrict__ whh_lo,
    const float* __restrict__ bhh,
    __nv_bfloat16* __restrict__ HHI_,        // [T*256,256]
    __nv_bfloat16* __restrict__ HLO_,
    unsigned int* __restrict__ flags)
{
    extern __shared__ char sm[];
    const uint32_t smb = smem_u32(sm);
    float* GHs = (float*)(sm + U_GH);
    const int tid = threadIdx.x;
    const int lane = tid & 31;
    const int wid = tid >> 5;
    const int mh = wid & 1;
    const int nh = wid >> 1;
    const int cta = blockIdx.x;
    const int b0 = (cta & 7) * 32;
    const int k0 = (cta >> 3) * 16;

    // ---- load W slice once (48 rows hi+lo) ----
    for (int i = tid; i < 1536; i += 128) {
        int j = i >> 5;
        int c = i & 31;
        int g = j >> 4, jr = j & 15;
        size_t soff = (size_t)(g * 256 + k0 + jr) * 256 + c * 8;
        uint32_t d = (uint32_t)(j * USTRIDE + c * 16);
        cp16(smb + U_WHI + d, whh_hi + soff);
        cp16(smb + U_WLO + d, whh_lo + soff);
    }
    CP_COMMIT();

    // zero GHs (used as-is at t=0)
    for (int i = tid; i < 32 * 49; i += 128) GHs[i] = 0.f;

    // ---- per-thread constants for gate phase ----
    int bloc[4], kloc[4];
    size_t off_o[4], gio[4];
    float brr[4], brz[4], brn[4];
    float hp[4];
    #pragma unroll
    for (int i = 0; i < 4; i++) {
        int idx = tid + 128 * i;
        int b = idx >> 4, ko = idx & 15;
        bloc[i] = b; kloc[i] = ko;
        int kg = k0 + ko, bg = b0 + b;
        off_o[i] = (size_t)bg * 256 + kg;
        gio[i] = (size_t)bg * 768 + kg;
        brr[i] = bhh[kg];
        brz[i] = bhh[256 + kg];
        brn[i] = bhh[512 + kg];
        hp[i] = 0.f;
    }

    // mma addressing
    const uint32_t a_row = (uint32_t)(lane & 15);
    const uint32_t a_kb  = (uint32_t)((lane >> 4) * 16);
    const uint32_t b_row = (uint32_t)(((lane >> 4) & 1) * 8 + (lane & 7));
    const uint32_t b_kb  = (uint32_t)(((lane >> 3) & 1) * 16);
    const uint32_t b2_row = (uint32_t)(lane & 7);
    const uint32_t b2_kb  = (uint32_t)(((lane >> 3) & 1) * 16);

    const uint32_t aBaseHi = smb + U_HHI + (uint32_t)(mh * 16 + a_row) * USTRIDE + a_kb;
    const uint32_t aBaseLo = smb + U_HLO + (uint32_t)(mh * 16 + a_row) * USTRIDE + a_kb;
    const uint32_t bBaseHi4 = smb + U_WHI + (uint32_t)(nh * 24 + b_row) * USTRIDE + b_kb;
    const uint32_t bBaseLo4 = smb + U_WLO + (uint32_t)(nh * 24 + b_row) * USTRIDE + b_kb;
    const uint32_t bBaseHi2 = smb + U_WHI + (uint32_t)(nh * 24 + 16 + b2_row) * USTRIDE + b2_kb;
    const uint32_t bBaseLo2 = smb + U_WLO + (uint32_t)(nh * 24 + 16 + b2_row) * USTRIDE + b2_kb;

    CP_WAIT0();
    __syncthreads();

    unsigned int* myflag = flags + cta;
    unsigned int* pollflag = flags + tid;   // NCTA == blockDim.x == 128

    for (int t = 0; t < TT; t++) {
        // ---- load h_prev tile (hi/lo) ----
        if (t > 0) {
            const __nv_bfloat16* hph = HHI_ + (size_t)(t - 1) * (BB * HH);
            const __nv_bfloat16* hpl = HLO_ + (size_t)(t - 1) * (BB * HH);
            for (int i = tid; i < 1024; i += 128) {
                int r = i >> 5;
                int c = i & 31;
                size_t soff = (size_t)(b0 + r) * 256 + c * 8;
                uint32_t d = (uint32_t)(r * USTRIDE + c * 16);
                cp16(smb + U_HHI + d, hph + soff);
                cp16(smb + U_HLO + d, hpl + soff);
            }
            CP_COMMIT();
        }

        // ---- prefetch gi for this step ----
        const float* gib = GI_ + (size_t)t * (BB * 768);
        float ir[4], iz[4], in_[4];
        #pragma unroll
        for (int i = 0; i < 4; i++) {
            ir[i]  = __ldg(gib + gio[i]);
            iz[i]  = __ldg(gib + gio[i] + 256);
            in_[i] = __ldg(gib + gio[i] + 512);
        }

        if (t > 0) {
            CP_WAIT0();
            __syncthreads();

            // ---- mma: M32 x N48 x K256, 3-term split ----
            float acc[3][4];
            #pragma unroll
            for (int i = 0; i < 3; i++)
                #pragma unroll
                for (int e = 0; e < 4; e++) acc[i][e] = 0.f;

            #pragma unroll 4
            for (int ks = 0; ks < 16; ks++) {
                const uint32_t koff = (uint32_t)(ks * 32);
                uint32_t a[4], bh[3][2], bl[3][2], r4[4];

                ldsm4(a, aBaseHi + koff);
                ldsm4(r4, bBaseHi4 + koff);
                bh[0][0] = r4[0]; bh[0][1] = r4[1]; bh[1][0] = r4[2]; bh[1][1] = r4[3];
                ldsm2(bh[2], bBaseHi2 + koff);
                #pragma unroll
                for (int nt = 0; nt < 3; nt++) mma16816(acc[nt], a, bh[nt]);

                ldsm4(r4, bBaseLo4 + koff);
                bl[0][0] = r4[0]; bl[0][1] = r4[1]; bl[1][0] = r4[2]; bl[1][1] = r4[3];
                ldsm2(bl[2], bBaseLo2 + koff);
                #pragma unroll
                for (int nt = 0; nt < 3; nt++) mma16816(acc[nt], a, bl[nt]);

                ldsm4(a, aBaseLo + koff);
                #pragma unroll
                for (int nt = 0; nt < 3; nt++) mma16816(acc[nt], a, bh[nt]);
            }

            // ---- store gh to smem ----
            {
                const int r0 = lane >> 2;
                const int cc = (lane & 3) * 2;
                #pragma unroll
                for (int nt = 0; nt < 3; nt++) {
                    int col = nh * 24 + nt * 8 + cc;
                    GHs[(mh * 16 + r0) * 49 + col]         = acc[nt][0];
                    GHs[(mh * 16 + r0) * 49 + col + 1]     = acc[nt][1];
                    GHs[(mh * 16 + r0 + 8) * 49 + col]     = acc[nt][2];
                    GHs[(mh * 16 + r0 + 8) * 49 + col + 1] = acc[nt][3];
                }
            }
            __syncthreads();
        }

        // ---- gates: 4 outputs per thread, hp in registers ----
        __nv_bfloat16* hoh = HHI_ + (size_t)t * (BB * HH);
        __nv_bfloat16* hol = HLO_ + (size_t)t * (BB * HH);
        #pragma unroll
        for (int i = 0; i < 4; i++) {
            int b = bloc[i], ko = kloc[i];
            float hr = GHs[b * 49 + ko]      + brr[i];
            float hz = GHs[b * 49 + 16 + ko] + brz[i];
            float hn = GHs[b * 49 + 32 + ko] + brn[i];

            float r = 1.f / (1.f + __expf(-(ir[i] + hr)));
            float z = 1.f / (1.f + __expf(-(iz[i] + hz)));
            float n = tanhf(in_[i] + r * hn);
            float hnew = (1.f - z) * n + z * hp[i];
            hp[i] = hnew;

            __nv_bfloat16 hh = __float2bfloat16(hnew);
            hoh[off_o[i]] = hh;
            hol[off_o[i]] = __float2bfloat16(hnew - __bfloat162float(hh));
        }

        // ---- grid barrier ----
        __threadfence();
        __syncthreads();
        if (tid == 0) {
            asm volatile("st.release.gpu.u32 [%0], %1;"
                :: "l"(myflag), "r"((unsigned int)(t + 1)) : "memory");
        }
        unsigned int target = (unsigned int)(t + 1);
        int done;
        do {
            unsigned int v;
            asm volatile("ld.acquire.gpu.u32 %0, [%1];"
                : "=r"(v) : "l"(pollflag) : "memory");
            done = __syncthreads_and(v >= target);
        } while (!done);
    }
}

// -------------------- fc2b head: out[M,18] = Q1[M,512] @ W[18,512]^T + b ---
__global__ void __launch_bounds__(256, 2) head_gemm(
    const float* __restrict__ A,
    const float* __restrict__ Wb,
    const float* __restrict__ bias,
    float* __restrict__ out, int M)
{
    __shared__ float Ws[18][512];
    const int tid = threadIdx.x;
    #pragma unroll
    for (int i = 0; i < 9; i++) {
        int idx = tid + 256 * i;
        ((float4*)&Ws[0][0])[idx] = ((const float4*)Wb)[idx];
    }
    __syncthreads();

    const size_t mbase = (size_t)blockIdx.x * 1024 + tid;

    float acc[4][18];
    #pragma unroll
    for (int i = 0; i < 4; i++)
        #pragma unroll
        for (int j = 0; j < 18; j++) acc[i][j] = 0.f;

    for (int k4 = 0; k4 < 128; k4++) {
        float4 a[4];
        #pragma unroll
        for (int i = 0; i < 4; i++)
            a[i] = *(const float4*)&A[(mbase + 256 * i) * 512 + k4 * 4];
        #pragma unroll
        for (int j = 0; j < 18; j++) {
            float4 w = *(const float4*)&Ws[j][k4 * 4];
            #pragma unroll
            for (int i = 0; i < 4; i++) {
                acc[i][j] += a[i].x * w.x;
                acc[i][j] += a[i].y * w.y;
                acc[i][j] += a[i].z * w.z;
                acc[i][j] += a[i].w * w.w;
            }
        }
    }

    #pragma unroll
    for (int i = 0; i < 4; i++) {
        size_t row = mbase + 256 * i;
        #pragma unroll
        for (int j = 0; j < 18; j++)
            out[row * 18 + j] = acc[i][j] + bias[j];
    }
}

// -------------------- launch ------------------------------------------------
extern "C" void kernel_launch(void* const* d_in, const int* in_sizes, int n_in,
                              void* d_out, int out_size)
{
    (void)in_sizes; (void)n_in; (void)out_size;
    const float* x    = (const float*)d_in[0];
    const float* W1a  = (const float*)d_in[1];
    const float* b1a  = (const float*)d_in[2];
    const float* W1b  = (const float*)d_in[3];
    const float* b1b  = (const float*)d_in[4];
    const float* Wih  = (const float*)d_in[5];
    const float* bih  = (const float*)d_in[6];
    const float* Whh  = (const float*)d_in[7];
    const float* bhh  = (const float*)d_in[8];
    const float* W2a  = (const float*)d_in[9];
    const float* b2a  = (const float*)d_in[10];
    const float* W2b  = (const float*)d_in[11];
    const float* b2b  = (const float*)d_in[12];
    float* out = (float*)d_out;

    float *buf1, *GI;
    __nv_bfloat16 *XHI, *XLO, *A1HI, *A1LO, *A2HI, *A2LO, *HHI, *HLO;
    __nv_bfloat16 *W1AHI, *W1ALO, *W1BHI, *W1BLO, *WIHHI, *WIHLO, *W2AHI, *W2ALO, *WHHHI, *WHHLO;
    unsigned int* FLAGS;

    cudaGetSymbolAddress((void**)&buf1, d_buf1);
    cudaGetSymbolAddress((void**)&GI,   d_GI);
    cudaGetSymbolAddress((void**)&XHI,  d_XHI);  cudaGetSymbolAddress((void**)&XLO,  d_XLO);
    cudaGetSymbolAddress((void**)&A1HI, d_A1HI); cudaGetSymbolAddress((void**)&A1LO, d_A1LO);
    cudaGetSymbolAddress((void**)&A2HI, d_A2HI); cudaGetSymbolAddress((void**)&A2LO, d_A2LO);
    cudaGetSymbolAddress((void**)&HHI,  d_HHI);  cudaGetSymbolAddress((void**)&HLO,  d_HLO);
    cudaGetSymbolAddress((void**)&W1AHI, d_W1AHI); cudaGetSymbolAddress((void**)&W1ALO, d_W1ALO);
    cudaGetSymbolAddress((void**)&W1BHI, d_W1BHI); cudaGetSymbolAddress((void**)&W1BLO, d_W1BLO);
    cudaGetSymbolAddress((void**)&WIHHI, d_WIHHI); cudaGetSymbolAddress((void**)&WIHLO, d_WIHLO);
    cudaGetSymbolAddress((void**)&W2AHI, d_W2AHI); cudaGetSymbolAddress((void**)&W2ALO, d_W2ALO);
    cudaGetSymbolAddress((void**)&WHHHI, d_WHHHI); cudaGetSymbolAddress((void**)&WHHLO, d_WHHLO);
    cudaGetSymbolAddress((void**)&FLAGS, d_flags);

    cudaFuncSetAttribute(gemm_bf<true, 0>,  cudaFuncAttributeMaxDynamicSharedMemorySize, G_SM_TOTAL);
    cudaFuncSetAttribute(gemm_bf<true, 1>,  cudaFuncAttributeMaxDynamicSharedMemorySize, G_SM_TOTAL);
    cudaFuncSetAttribute(gemm_bf<false, 0>, cudaFuncAttributeMaxDynamicSharedMemorySize, G_SM_TOTAL);
    cudaFuncSetAttribute(gru_persist, cudaFuncAttributeMaxDynamicSharedMemorySize, U_SM_TOTAL);

    const int M = MTOT;

    // ---- pre-split inputs/weights to bf16 hi/lo ----
    split_f32<<<(M * 256 / 4 + 255) / 256, 256>>>((const float4*)x, (uint2*)XHI, (uint2*)XLO, M * 256 / 4);
    split_f32<<<128, 256>>>((const float4*)W1a, (uint2*)W1AHI, (uint2*)W1ALO, 512 * 256 / 4);
    split_f32<<<128, 256>>>((const float4*)W1b, (uint2*)W1BHI, (uint2*)W1BLO, 256 * 512 / 4);
    split_f32<<<192, 256>>>((const float4*)Wih, (uint2*)WIHHI, (uint2*)WIHLO, 768 * 256 / 4);
    split_f32<<<128, 256>>>((const float4*)W2a, (uint2*)W2AHI, (uint2*)W2ALO, 512 * 256 / 4);
    split_f32<<<192, 256>>>((const float4*)Whh, (uint2*)WHHHI, (uint2*)WHHLO, 768 * 256 / 4);

    zero_u32<<<1, NCTA>>>(FLAGS, NCTA);

    // ---- batched GEMMs ----
    gemm_bf<true, 1><<<dim3(4, M / 128), 256, G_SM_TOTAL>>>(
        XHI, XLO, W1AHI, W1ALO, b1a, nullptr, A1HI, A1LO, M, 512, 256);
    gemm_bf<true, 1><<<dim3(2, M / 128), 256, G_SM_TOTAL>>>(
        A1HI, A1LO, W1BHI, W1BLO, b1b, nullptr, A2HI, A2LO, M, 256, 512);
    gemm_bf<false, 0><<<dim3(6, M / 128), 256, G_SM_TOTAL>>>(
        A2HI, A2LO, WIHHI, WIHLO, bih, GI, nullptr, nullptr, M, 768, 256);

    // ---- persistent GRU: all 512 steps in one launch ----
    gru_persist<<<NCTA, 128, U_SM_TOTAL>>>(GI, WHHHI, WHHLO, bhh, HHI, HLO, FLAGS);

    // fc2a + head
    gemm_bf<true, 0><<<dim3(4, M / 128), 256, G_SM_TOTAL>>>(
        HHI, HLO, W2AHI, W2ALO, b2a, buf1, nullptr, nullptr, M, 512, 256);
    head_gemm<<<M / 1024, 256>>>(buf1, W2b, b2b, out, M);
}